// round 9
// baseline (speedup 1.0000x reference)
#include <cuda_runtime.h>
#include <cuda_bf16.h>
#include <stdint.h>

#define IN_F   4096
#define OUT_F  11008
#define BATCH  16
#define SPLITS 8
#define KSTEPS_TOT   (IN_F / 16)            // 256 k16-steps
#define KSTEPS_SPLIT (KSTEPS_TOT / SPLITS)  // 32
#define CKS    8                            // ksteps per smem chunk
#define NCHUNK (KSTEPS_SPLIT / CKS)         // 4
#define MTILE  64
#define THREADS 128

// Static scratch (allocations forbidden).
__device__ __align__(16) uint32_t g_bfrag[KSTEPS_TOT * 256];      // [ks][reg(8)][lane(32)]
__device__ __align__(16) float    g_part[SPLITS * BATCH * OUT_F]; // [s][b][o]

// Pack (k_even, k_odd) floats into one bf16x2 reg (low = even k).
__device__ __forceinline__ uint32_t pack_bf16x2(float ev, float od) {
    __nv_bfloat162 h = __floats2bfloat162_rn(ev, od);   // .x = ev (low), .y = od (high)
    return *(uint32_t*)&h;
}

// m16n8k16 row.col bf16 MMA, fp32 accumulate in place.
__device__ __forceinline__ void mma16816(float* c, const uint32_t* a, uint32_t b0, uint32_t b1) {
    asm volatile(
        "mma.sync.aligned.m16n8k16.row.col.f32.bf16.bf16.f32 "
        "{%0,%1,%2,%3}, {%4,%5,%6,%7}, {%8,%9}, {%0,%1,%2,%3};"
        : "+f"(c[0]), "+f"(c[1]), "+f"(c[2]), "+f"(c[3])
        : "r"(a[0]), "r"(a[1]), "r"(a[2]), "r"(a[3]), "r"(b0), "r"(b1));
}

// ---------------------------------------------------------------------------
// Kernel 1: build B fragments. B[k][n]: n<16 -> hi(x[n][k]), n>=16 -> lo.
// Fragment reg r = j*2 + p for n-tile j (n = j*8 + g), p = b0/b1 (k0/k8).
// One thread per (ks, lane): writes 8 regs.
// ---------------------------------------------------------------------------
__global__ void prep_kernel(const float* __restrict__ x) {
    int idx = blockIdx.x * blockDim.x + threadIdx.x;   // 256*32 = 8192
    int ks = idx >> 5, l = idx & 31;
    int g = l >> 2, t = l & 3;
    int kk = ks * 16 + 2 * t;

    uint32_t* dst = g_bfrag + ks * 256 + l;
#pragma unroll
    for (int rr = 0; rr < 2; rr++) {                   // batch rows g, g+8
        const float* xr = x + (size_t)(g + rr * 8) * IN_F + kk;
        float v0 = xr[0], v1 = xr[1], v2 = xr[8], v3 = xr[9];
        __nv_bfloat16 h0 = __float2bfloat16(v0), h1 = __float2bfloat16(v1);
        __nv_bfloat16 h2 = __float2bfloat16(v2), h3 = __float2bfloat16(v3);
        // hi tiles (j = rr)
        dst[(rr * 2 + 0) * 32] = pack_bf16x2(__bfloat162float(h0), __bfloat162float(h1));
        dst[(rr * 2 + 1) * 32] = pack_bf16x2(__bfloat162float(h2), __bfloat162float(h3));
        // lo tiles (j = rr + 2)
        dst[((rr + 2) * 2 + 0) * 32] =
            pack_bf16x2(v0 - __bfloat162float(h0), v1 - __bfloat162float(h1));
        dst[((rr + 2) * 2 + 1) * 32] =
            pack_bf16x2(v2 - __bfloat162float(h2), v3 - __bfloat162float(h3));
    }
}

// ---------------------------------------------------------------------------
// Kernel 2: HMMA GEMM. Warp owns 16 output rows; A frags LDG'd straight from
// the int32 weight stream (depth-2 reg prefetch) and converted in regs;
// B frags from double-buffered smem. Split-K over grid.y.
// ---------------------------------------------------------------------------
__global__ void __launch_bounds__(THREADS) gemm_kernel(const int* __restrict__ W) {
    __shared__ __align__(16) uint32_t sb[2 * CKS * 256];   // 2 x 8 KB

    const int tid = threadIdx.x, wid = tid >> 5, l = tid & 31;
    const int g = l >> 2, t = l & 3;
    const int s = blockIdx.y;
    const int m0 = blockIdx.x * MTILE + wid * 16;
    const int ksbase = s * KSTEPS_SPLIT;

    const int* rowA  = W + (size_t)(m0 + g) * IN_F;
    const int* rowA8 = rowA + (size_t)8 * IN_F;

    // A prefetch ring (depth 2). Frag order: a0=[g][k0], a1=[g+8][k0], a2=[g][k8], a3=[g+8][k8]
    int2 ar[2][4];
#define LDA(i, buf) do {                                      \
        int _kk = (ksbase + (i)) * 16 + 2 * t;                \
        ar[buf][0] = *(const int2*)(rowA  + _kk);             \
        ar[buf][1] = *(const int2*)(rowA8 + _kk);             \
        ar[buf][2] = *(const int2*)(rowA  + _kk + 8);         \
        ar[buf][3] = *(const int2*)(rowA8 + _kk + 8);         \
    } while (0)

    const uint4* bsrc = (const uint4*)(g_bfrag + ksbase * 256);

    float acc[16];
#pragma unroll
    for (int i = 0; i < 16; i++) acc[i] = 0.f;

    // Preload B chunk 0 into smem, A ksteps 0,1 into regs.
    uint4 stage[4];
#pragma unroll
    for (int j = 0; j < 4; j++) stage[j] = bsrc[j * 128 + tid];
#pragma unroll
    for (int j = 0; j < 4; j++) ((uint4*)sb)[j * 128 + tid] = stage[j];
    LDA(0, 0);
    LDA(1, 1);
    __syncthreads();

    int p = 0;
    for (int c = 0; c < NCHUNK; c++) {
        if (c + 1 < NCHUNK) {          // prefetch next B chunk into regs
#pragma unroll
            for (int j = 0; j < 4; j++) stage[j] = bsrc[(c + 1) * 512 + j * 128 + tid];
        }

        const uint32_t* bbuf = sb + p * (CKS * 256);
#pragma unroll
        for (int ksl = 0; ksl < CKS; ksl++) {
            int i = c * CKS + ksl;
            int buf = i & 1;
            uint32_t a[4];
#pragma unroll
            for (int q = 0; q < 4; q++)
                a[q] = pack_bf16x2((float)ar[buf][q].x, (float)ar[buf][q].y);
            if (i + 2 < KSTEPS_SPLIT) LDA(i + 2, buf);   // refill slot just consumed

            uint32_t bw[8];
#pragma unroll
            for (int r = 0; r < 8; r++) bw[r] = bbuf[ksl * 256 + r * 32 + l];

            mma16816(acc + 0,  a, bw[0], bw[1]);   // n-tile 0 (hi b0..7)
            mma16816(acc + 4,  a, bw[2], bw[3]);   // n-tile 1 (hi b8..15)
            mma16816(acc + 8,  a, bw[4], bw[5]);   // n-tile 2 (lo b0..7)
            mma16816(acc + 12, a, bw[6], bw[7]);   // n-tile 3 (lo b8..15)
        }

        if (c + 1 < NCHUNK) {
#pragma unroll
            for (int j = 0; j < 4; j++) ((uint4*)sb)[(p ^ 1) * 512 + j * 128 + tid] = stage[j];
        }
        __syncthreads();
        p ^= 1;
    }

    // Epilogue: hi + lo, store partials. C frag: c0=[g][2t], c1=[g][2t+1], c2=[g+8][2t], c3=[g+8][2t+1]
    float* pb = g_part + (size_t)s * (BATCH * OUT_F);
#pragma unroll
    for (int j = 0; j < 2; j++) {
        int b0 = j * 8 + 2 * t;
        float v0 = acc[j * 4 + 0] + acc[(j + 2) * 4 + 0];
        float v1 = acc[j * 4 + 1] + acc[(j + 2) * 4 + 1];
        float v2 = acc[j * 4 + 2] + acc[(j + 2) * 4 + 2];
        float v3 = acc[j * 4 + 3] + acc[(j + 2) * 4 + 3];
        pb[(size_t)(b0)     * OUT_F + m0 + g]     = v0;
        pb[(size_t)(b0 + 1) * OUT_F + m0 + g]     = v1;
        pb[(size_t)(b0)     * OUT_F + m0 + g + 8] = v2;
        pb[(size_t)(b0 + 1) * OUT_F + m0 + g + 8] = v3;
    }
}

// ---------------------------------------------------------------------------
// Kernel 3: sum the 8 split partials (fixed order), apply scale + bias.
// Loads forced into a live array first -> 8 float4 loads in flight (MLP).
// ---------------------------------------------------------------------------
__global__ void __launch_bounds__(256) reduce_kernel(const float* __restrict__ scale,
                                                     const float* __restrict__ bias,
                                                     float* __restrict__ out) {
    const int NV = BATCH * OUT_F / 4;
    int e = blockIdx.x * blockDim.x + threadIdx.x;
    if (e >= NV) return;
    int o4 = e % (OUT_F / 4);

    float4 v[SPLITS];
#pragma unroll
    for (int s = 0; s < SPLITS; s++)
        v[s] = ((const float4*)g_part)[(size_t)s * NV + e];

    // Fixed-order pairwise tree sum (deterministic).
#pragma unroll
    for (int st = 1; st < SPLITS; st <<= 1)
#pragma unroll
        for (int i = 0; i < SPLITS; i += 2 * st) {
            v[i].x += v[i + st].x; v[i].y += v[i + st].y;
            v[i].z += v[i + st].z; v[i].w += v[i + st].w;
        }

    float4 sc = ((const float4*)scale)[o4];
    float4 bi = ((const float4*)bias)[o4];
    float4 r;
    r.x = fmaf(v[0].x, sc.x, bi.x);
    r.y = fmaf(v[0].y, sc.y, bi.y);
    r.z = fmaf(v[0].z, sc.z, bi.z);
    r.w = fmaf(v[0].w, sc.w, bi.w);
    ((float4*)out)[e] = r;
}

extern "C" void kernel_launch(void* const* d_in, const int* in_sizes, int n_in,
                              void* d_out, int out_size) {
    const float* x     = (const float*)d_in[0];
    const int*   W     = (const int*)d_in[1];
    const float* scale = (const float*)d_in[2];
    const float* bias  = (const float*)d_in[3];
    float*       out   = (float*)d_out;

    prep_kernel<<<(KSTEPS_TOT * 32) / 256, 256>>>(x);

    dim3 grid(OUT_F / MTILE, SPLITS);          // 172 x 8 = 1376 CTAs
    gemm_kernel<<<grid, THREADS>>>(W);

    int nv = BATCH * OUT_F / 4;
    reduce_kernel<<<(nv + 255) / 256, 256>>>(scale, bias, out);
}

// round 12
// speedup vs baseline: 1.1813x; 1.1813x over previous
#include <cuda_runtime.h>
#include <cuda_bf16.h>
#include <stdint.h>

#define IN_F   4096
#define OUT_F  11008
#define BATCH  16
#define SPLITS 4
#define KSTEPS_TOT   (IN_F / 16)            // 256 k16-steps
#define KSTEPS_SPLIT (KSTEPS_TOT / SPLITS)  // 64
#define CKS    8                            // ksteps per smem chunk
#define NCHUNK (KSTEPS_SPLIT / CKS)         // 8
#define MTILE  64
#define THREADS 128

// Static scratch (allocations forbidden).
__device__ __align__(16) uint32_t g_bfrag[KSTEPS_TOT * 256];      // [ks][reg(8)][lane(32)]
__device__ __align__(16) float    g_part[SPLITS * BATCH * OUT_F]; // [s][b][o]

// Pack (k_even, k_odd) floats into one bf16x2 reg (low = even k).
__device__ __forceinline__ uint32_t pack_bf16x2(float ev, float od) {
    __nv_bfloat162 h = __floats2bfloat162_rn(ev, od);   // .x = ev (low), .y = od (high)
    return *(uint32_t*)&h;
}

// m16n8k16 row.col bf16 MMA, fp32 accumulate in place.
__device__ __forceinline__ void mma16816(float* c, const uint32_t* a, uint32_t b0, uint32_t b1) {
    asm volatile(
        "mma.sync.aligned.m16n8k16.row.col.f32.bf16.bf16.f32 "
        "{%0,%1,%2,%3}, {%4,%5,%6,%7}, {%8,%9}, {%0,%1,%2,%3};"
        : "+f"(c[0]), "+f"(c[1]), "+f"(c[2]), "+f"(c[3])
        : "r"(a[0]), "r"(a[1]), "r"(a[2]), "r"(a[3]), "r"(b0), "r"(b1));
}

// ---------------------------------------------------------------------------
// Kernel 1: build B fragments, ONE THREAD PER FRAGMENT REG (65536 threads).
// idx = ks*256 + r*32 + l.  r = j*2 + p:  n-tile j (0,1 hi / 2,3 lo of batch
// rows (j&1)*8+g),  p selects k0/k8 halves.  Fully coalesced 128B stores.
// ---------------------------------------------------------------------------
__global__ void prep_kernel(const float* __restrict__ x) {
    int idx = blockIdx.x * blockDim.x + threadIdx.x;   // KSTEPS_TOT*256 = 65536
    int l  = idx & 31;
    int r  = (idx >> 5) & 7;
    int ks = idx >> 8;
    int g = l >> 2, t = l & 3;
    int j = r >> 1, p = r & 1;
    int br = (j & 1) * 8 + g;
    int k  = ks * 16 + 2 * t + 8 * p;

    float2 v = *(const float2*)(x + (size_t)br * IN_F + k);
    float h0 = __bfloat162float(__float2bfloat16(v.x));
    float h1 = __bfloat162float(__float2bfloat16(v.y));
    uint32_t out;
    if (j < 2) out = pack_bf16x2(h0, h1);              // hi part
    else       out = pack_bf16x2(v.x - h0, v.y - h1);  // lo residual
    g_bfrag[idx] = out;
}

// ---------------------------------------------------------------------------
// Kernel 2: HMMA GEMM (R6 mainloop, SPLITS=4). Warp owns 16 output rows; A
// frags LDG'd from the int32 weight stream (depth-2 reg prefetch), converted
// in regs; B frags from double-buffered smem. Epilogue transposed via smem.
// ---------------------------------------------------------------------------
__global__ void __launch_bounds__(THREADS) gemm_kernel(const int* __restrict__ W) {
    __shared__ __align__(16) uint32_t sb[2 * CKS * 256];   // 2 x 8 KB

    const int tid = threadIdx.x, wid = tid >> 5, l = tid & 31;
    const int g = l >> 2, t = l & 3;
    const int s = blockIdx.y;
    const int m0 = blockIdx.x * MTILE + wid * 16;
    const int ksbase = s * KSTEPS_SPLIT;

    const int* rowA  = W + (size_t)(m0 + g) * IN_F;
    const int* rowA8 = rowA + (size_t)8 * IN_F;

    // A prefetch ring (depth 2). Frag order: a0=[g][k0], a1=[g+8][k0], a2=[g][k8], a3=[g+8][k8]
    int2 ar[2][4];
#define LDA(i, buf) do {                                      \
        int _kk = (ksbase + (i)) * 16 + 2 * t;                \
        ar[buf][0] = *(const int2*)(rowA  + _kk);             \
        ar[buf][1] = *(const int2*)(rowA8 + _kk);             \
        ar[buf][2] = *(const int2*)(rowA  + _kk + 8);         \
        ar[buf][3] = *(const int2*)(rowA8 + _kk + 8);         \
    } while (0)

    const uint4* bsrc = (const uint4*)(g_bfrag + ksbase * 256);

    float acc[16];
#pragma unroll
    for (int i = 0; i < 16; i++) acc[i] = 0.f;

    // Preload B chunk 0 into smem, A ksteps 0,1 into regs.
    uint4 stage[4];
#pragma unroll
    for (int j = 0; j < 4; j++) stage[j] = bsrc[j * 128 + tid];
#pragma unroll
    for (int j = 0; j < 4; j++) ((uint4*)sb)[j * 128 + tid] = stage[j];
    LDA(0, 0);
    LDA(1, 1);
    __syncthreads();

    int p = 0;
    for (int c = 0; c < NCHUNK; c++) {
        if (c + 1 < NCHUNK) {          // prefetch next B chunk into regs
#pragma unroll
            for (int j = 0; j < 4; j++) stage[j] = bsrc[(c + 1) * 512 + j * 128 + tid];
        }

        const uint32_t* bbuf = sb + p * (CKS * 256);
#pragma unroll
        for (int ksl = 0; ksl < CKS; ksl++) {
            int i = c * CKS + ksl;
            int buf = i & 1;
            uint32_t a[4];
#pragma unroll
            for (int q = 0; q < 4; q++)
                a[q] = pack_bf16x2((float)ar[buf][q].x, (float)ar[buf][q].y);
            if (i + 2 < KSTEPS_SPLIT) LDA(i + 2, buf);   // refill slot just consumed

            uint32_t bw[8];
#pragma unroll
            for (int r = 0; r < 8; r++) bw[r] = bbuf[ksl * 256 + r * 32 + l];

            mma16816(acc + 0,  a, bw[0], bw[1]);   // n-tile 0 (hi b0..7)
            mma16816(acc + 4,  a, bw[2], bw[3]);   // n-tile 1 (hi b8..15)
            mma16816(acc + 8,  a, bw[4], bw[5]);   // n-tile 2 (lo b0..7)
            mma16816(acc + 12, a, bw[6], bw[7]);   // n-tile 3 (lo b8..15)
        }

        if (c + 1 < NCHUNK) {
#pragma unroll
            for (int j = 0; j < 4; j++) ((uint4*)sb)[(p ^ 1) * 512 + j * 128 + tid] = stage[j];
        }
        __syncthreads();
        p ^= 1;
    }

    // Epilogue: hi + lo, transpose through smem (reuse sb), coalesced stores.
    // C frag: c0=[g][2t], c1=[g][2t+1], c2=[g+8][2t], c3=[g+8][2t+1]
    float* sep = (float*)sb;                       // [b][m_local] = 16 x 64 floats
#pragma unroll
    for (int j = 0; j < 2; j++) {
        int b0 = j * 8 + 2 * t;
        int ml = wid * 16 + g;
        sep[(b0)     * MTILE + ml]     = acc[j * 4 + 0] + acc[(j + 2) * 4 + 0];
        sep[(b0 + 1) * MTILE + ml]     = acc[j * 4 + 1] + acc[(j + 2) * 4 + 1];
        sep[(b0)     * MTILE + ml + 8] = acc[j * 4 + 2] + acc[(j + 2) * 4 + 2];
        sep[(b0 + 1) * MTILE + ml + 8] = acc[j * 4 + 3] + acc[(j + 2) * 4 + 3];
    }
    __syncthreads();

    float* pb = g_part + (size_t)s * (BATCH * OUT_F) + blockIdx.x * MTILE;
#pragma unroll
    for (int f = tid; f < BATCH * MTILE / 4; f += THREADS) {   // 256 float4s
        int b   = f >> 4;
        int seg = f & 15;
        float4 v = ((const float4*)sep)[f];
        *(float4*)(pb + (size_t)b * OUT_F + seg * 4) = v;
    }
}

// ---------------------------------------------------------------------------
// Kernel 3: sum the 4 split partials (fixed order), apply scale + bias.
// ---------------------------------------------------------------------------
__global__ void __launch_bounds__(256) reduce_kernel(const float* __restrict__ scale,
                                                     const float* __restrict__ bias,
                                                     float* __restrict__ out) {
    const int NV = BATCH * OUT_F / 4;
    int e = blockIdx.x * blockDim.x + threadIdx.x;
    if (e >= NV) return;
    int o4 = e % (OUT_F / 4);

    float4 v[SPLITS];
#pragma unroll
    for (int s = 0; s < SPLITS; s++)
        v[s] = ((const float4*)g_part)[(size_t)s * NV + e];

    float4 sum;
    sum.x = (v[0].x + v[1].x) + (v[2].x + v[3].x);
    sum.y = (v[0].y + v[1].y) + (v[2].y + v[3].y);
    sum.z = (v[0].z + v[1].z) + (v[2].z + v[3].z);
    sum.w = (v[0].w + v[1].w) + (v[2].w + v[3].w);

    float4 sc = ((const float4*)scale)[o4];
    float4 bi = ((const float4*)bias)[o4];
    float4 r;
    r.x = fmaf(sum.x, sc.x, bi.x);
    r.y = fmaf(sum.y, sc.y, bi.y);
    r.z = fmaf(sum.z, sc.z, bi.z);
    r.w = fmaf(sum.w, sc.w, bi.w);
    ((float4*)out)[e] = r;
}

extern "C" void kernel_launch(void* const* d_in, const int* in_sizes, int n_in,
                              void* d_out, int out_size) {
    const float* x     = (const float*)d_in[0];
    const int*   W     = (const int*)d_in[1];
    const float* scale = (const float*)d_in[2];
    const float* bias  = (const float*)d_in[3];
    float*       out   = (float*)d_out;

    prep_kernel<<<(KSTEPS_TOT * 256) / 256, 256>>>(x);

    dim3 grid(OUT_F / MTILE, SPLITS);          // 172 x 4 = 688 CTAs
    gemm_kernel<<<grid, THREADS>>>(W);

    int nv = BATCH * OUT_F / 4;
    reduce_kernel<<<(nv + 255) / 256, 256>>>(scale, bias, out);
}